// round 1
// baseline (speedup 1.0000x reference)
#include <cuda_runtime.h>
#include <math.h>

#define EPSV 1e-6f

constexpr int B = 2, S = 1024, D = 1024, H = 16, HD = 64;
constexpr int BS = B * S;                 // 2048
constexpr size_t PROJ_ELEMS = (size_t)BS * D;       // 2M
constexpr size_t ATTN_ELEMS = (size_t)B * H * S * S; // 32M

// Scratch (device globals — no dynamic allocation allowed)
__device__ float g_qm[PROJ_ELEMS];
__device__ float g_km[PROJ_ELEMS];
__device__ float g_vm[PROJ_ELEMS];
__device__ float g_vvar[PROJ_ELEMS];
__device__ float g_ym[PROJ_ELEMS];
__device__ float g_p[PROJ_ELEMS];
__device__ float g_logits[ATTN_ELEMS];
__device__ float g_amu[ATTN_ELEMS];
__device__ float g_avar[ATTN_ELEMS];

// ---------------------------------------------------------------------------
// GEMM-NT: C[M,N] = op(A)[M,K] * op(B)[N,K]^T  (+ epilogue)
// op = optional elementwise square. 128x128 block tile, TK=8, 256 threads, 8x8 microtile.
// EPI: 0 = +bias[n];  1 = (sqrt(acc)+eps)^2;  2 = sqrt(acc)
// Requires M%128==0, N%128==0, K%8==0 (holds: 2048/1024/1024).
// ---------------------------------------------------------------------------
template<bool SQA, bool SQB, int EPI>
__global__ void __launch_bounds__(256) gemm_nt(
    float* __restrict__ C, const float* __restrict__ A, const float* __restrict__ Bm,
    const float* __restrict__ bias, int M, int N, int K)
{
    __shared__ float as[8][132];
    __shared__ float bs[8][132];

    const int tid = threadIdx.x;
    const int bx = blockIdx.x, by = blockIdx.y;
    const int arow = tid >> 1;             // 0..127
    const int ac4  = (tid & 1) * 4;        // 0 or 4
    const float* Ap = A  + (size_t)(by * 128 + arow) * K + ac4;
    const float* Bp = Bm + (size_t)(bx * 128 + arow) * K + ac4;

    const int ty = tid >> 4, tx = tid & 15;

    float acc[8][8];
    #pragma unroll
    for (int i = 0; i < 8; i++)
        #pragma unroll
        for (int j = 0; j < 8; j++) acc[i][j] = 0.f;

    for (int k0 = 0; k0 < K; k0 += 8) {
        float4 av = *(const float4*)(Ap + k0);
        float4 bv = *(const float4*)(Bp + k0);
        if (SQA) { av.x *= av.x; av.y *= av.y; av.z *= av.z; av.w *= av.w; }
        if (SQB) { bv.x *= bv.x; bv.y *= bv.y; bv.z *= bv.z; bv.w *= bv.w; }
        __syncthreads();
        as[ac4 + 0][arow] = av.x; as[ac4 + 1][arow] = av.y;
        as[ac4 + 2][arow] = av.z; as[ac4 + 3][arow] = av.w;
        bs[ac4 + 0][arow] = bv.x; bs[ac4 + 1][arow] = bv.y;
        bs[ac4 + 2][arow] = bv.z; bs[ac4 + 3][arow] = bv.w;
        __syncthreads();
        #pragma unroll
        for (int kk = 0; kk < 8; kk++) {
            float a[8], b[8];
            #pragma unroll
            for (int i = 0; i < 8; i++) a[i] = as[kk][ty * 8 + i];
            #pragma unroll
            for (int j = 0; j < 8; j++) b[j] = bs[kk][tx * 8 + j];
            #pragma unroll
            for (int i = 0; i < 8; i++)
                #pragma unroll
                for (int j = 0; j < 8; j++)
                    acc[i][j] = fmaf(a[i], b[j], acc[i][j]);
        }
    }

    const int row0 = by * 128 + ty * 8;
    const int col0 = bx * 128 + tx * 8;
    #pragma unroll
    for (int i = 0; i < 8; i++) {
        #pragma unroll
        for (int j = 0; j < 8; j++) {
            float v = acc[i][j];
            if (EPI == 0) {
                v += bias[col0 + j];
            } else if (EPI == 1) {
                float sv = sqrtf(v) + EPSV;
                v = sv * sv;
            } else { // EPI == 2
                v = sqrtf(v);
            }
            C[(size_t)(row0 + i) * N + col0 + j] = v;
        }
    }
}

// ---------------------------------------------------------------------------
// QK^T per head: logits[b,h,s,t] = dot(qm[b,s,h*64:], km[b,t,h*64:]) / (8*tau)
// 64x64 output tile, full K=64 in smem. grid (S/64, S/64, B*H), 256 threads.
// ---------------------------------------------------------------------------
__global__ void __launch_bounds__(256) qk_kernel(
    float* __restrict__ logits, const float* __restrict__ qm,
    const float* __restrict__ km, const float* __restrict__ tau)
{
    __shared__ float qs[64][66];
    __shared__ float ks[64][66];

    const int tid = threadIdx.x;
    const int bh = blockIdx.z;
    const int b = bh >> 4, h = bh & 15;
    const int s0 = blockIdx.y * 64, t0 = blockIdx.x * 64;

    const float* Qb = qm + (size_t)b * S * D + h * HD;
    const float* Kb = km + (size_t)b * S * D + h * HD;

    const int lr  = tid >> 4;        // 0..15
    const int lc4 = (tid & 15) * 4;  // 0..60
    #pragma unroll
    for (int it = 0; it < 4; it++) {
        int r = lr + it * 16;
        float4 qv = *(const float4*)(Qb + (size_t)(s0 + r) * D + lc4);
        float4 kv = *(const float4*)(Kb + (size_t)(t0 + r) * D + lc4);
        qs[lc4 + 0][r] = qv.x; qs[lc4 + 1][r] = qv.y;
        qs[lc4 + 2][r] = qv.z; qs[lc4 + 3][r] = qv.w;
        ks[lc4 + 0][r] = kv.x; ks[lc4 + 1][r] = kv.y;
        ks[lc4 + 2][r] = kv.z; ks[lc4 + 3][r] = kv.w;
    }
    __syncthreads();

    const int ty = tid >> 4, tx = tid & 15;
    float acc[4][4];
    #pragma unroll
    for (int i = 0; i < 4; i++)
        #pragma unroll
        for (int j = 0; j < 4; j++) acc[i][j] = 0.f;

    #pragma unroll 8
    for (int k = 0; k < 64; k++) {
        float a[4], bb[4];
        #pragma unroll
        for (int i = 0; i < 4; i++) a[i]  = qs[k][ty * 4 + i];
        #pragma unroll
        for (int j = 0; j < 4; j++) bb[j] = ks[k][tx * 4 + j];
        #pragma unroll
        for (int i = 0; i < 4; i++)
            #pragma unroll
            for (int j = 0; j < 4; j++)
                acc[i][j] = fmaf(a[i], bb[j], acc[i][j]);
    }

    const float scale = 1.f / (8.f * tau[0]);
    float* Lb = logits + (size_t)bh * S * S;
    #pragma unroll
    for (int i = 0; i < 4; i++)
        #pragma unroll
        for (int j = 0; j < 4; j++)
            Lb[(size_t)(s0 + ty * 4 + i) * S + t0 + tx * 4 + j] = acc[i][j] * scale;
}

// ---------------------------------------------------------------------------
// Dual-temperature softmax over rows of 1024.
//   top  = softmax(x)            rest = softmax(x / c)
//   amu  = top + rest            avar = 1e-4 + rest*(1-rest)*l_var + eps
// One block per row (B*H*S rows), 256 threads * float4.
// ---------------------------------------------------------------------------
__global__ void __launch_bounds__(256) softmax_kernel(
    float* __restrict__ amu, float* __restrict__ avar,
    const float* __restrict__ logits, const float* __restrict__ tau)
{
    __shared__ float shm[8], sh1[8], sh2[8];
    const int tid = threadIdx.x;
    const size_t row = blockIdx.x;
    const float4 v = ((const float4*)(logits + row * (size_t)S))[tid];

    // row max
    float m = fmaxf(fmaxf(v.x, v.y), fmaxf(v.z, v.w));
    #pragma unroll
    for (int o = 16; o; o >>= 1) m = fmaxf(m, __shfl_xor_sync(0xffffffffu, m, o));
    if ((tid & 31) == 0) shm[tid >> 5] = m;
    __syncthreads();
    m = shm[tid & 7];
    #pragma unroll
    for (int o = 4; o; o >>= 1) m = fmaxf(m, __shfl_xor_sync(0xffffffffu, m, o));

    const float tv = tau[0];
    const float l_var = ((0.1f + EPSV) / 64.f + EPSV) / (tv * tv) + EPSV;
    const float invc = rsqrtf(1.f + 0.39269908169872414f * l_var); // pi/8

    float4 e1, e2;
    e1.x = expf(v.x - m); e1.y = expf(v.y - m); e1.z = expf(v.z - m); e1.w = expf(v.w - m);
    e2.x = expf((v.x - m) * invc); e2.y = expf((v.y - m) * invc);
    e2.z = expf((v.z - m) * invc); e2.w = expf((v.w - m) * invc);

    float s1 = e1.x + e1.y + e1.z + e1.w;
    float s2 = e2.x + e2.y + e2.z + e2.w;
    #pragma unroll
    for (int o = 16; o; o >>= 1) {
        s1 += __shfl_xor_sync(0xffffffffu, s1, o);
        s2 += __shfl_xor_sync(0xffffffffu, s2, o);
    }
    if ((tid & 31) == 0) { sh1[tid >> 5] = s1; sh2[tid >> 5] = s2; }
    __syncthreads();
    s1 = sh1[tid & 7];
    s2 = sh2[tid & 7];
    #pragma unroll
    for (int o = 4; o; o >>= 1) {
        s1 += __shfl_xor_sync(0xffffffffu, s1, o);
        s2 += __shfl_xor_sync(0xffffffffu, s2, o);
    }

    const float r1 = 1.f / s1, r2 = 1.f / s2;
    float4 mu4, var4;
    {
        float t, r;
        t = e1.x * r1; r = e2.x * r2; mu4.x = t + r; var4.x = 1e-4f + r * (1.f - r) * l_var + EPSV;
        t = e1.y * r1; r = e2.y * r2; mu4.y = t + r; var4.y = 1e-4f + r * (1.f - r) * l_var + EPSV;
        t = e1.z * r1; r = e2.z * r2; mu4.z = t + r; var4.z = 1e-4f + r * (1.f - r) * l_var + EPSV;
        t = e1.w * r1; r = e2.w * r2; mu4.w = t + r; var4.w = 1e-4f + r * (1.f - r) * l_var + EPSV;
    }
    ((float4*)(amu  + row * (size_t)S))[tid] = mu4;
    ((float4*)(avar + row * (size_t)S))[tid] = var4;
}

// ---------------------------------------------------------------------------
// AV: Y[b, s, h*64+hd] = sum_t Attn[b,h,s,t] * V[b, t, h*64+hd]
// Writes directly in merged [B,S,D] layout. 64(s) x 64(hd) tile, K-chunks of 64.
// grid (S/64, B*H). EPI: 0 = raw; 1 = (sqrt(acc+eps)+eps)^2 (for variance path)
// ---------------------------------------------------------------------------
template<int EPI>
__global__ void __launch_bounds__(256) av_kernel(
    float* __restrict__ Y, const float* __restrict__ Attn, const float* __restrict__ V)
{
    __shared__ float ast[64][66];
    __shared__ float vs[64][64];

    const int tid = threadIdx.x;
    const int bh = blockIdx.y;
    const int b = bh >> 4, h = bh & 15;
    const int s0 = blockIdx.x * 64;

    const float* Ab = Attn + (size_t)bh * S * S;
    const float* Vb = V + (size_t)b * S * D + h * HD;
    float* Yb = Y + (size_t)b * S * D + h * HD;

    const int ty = tid >> 4, tx = tid & 15;
    const int lr = tid >> 4, lc4 = (tid & 15) * 4;

    float acc[4][4];
    #pragma unroll
    for (int i = 0; i < 4; i++)
        #pragma unroll
        for (int j = 0; j < 4; j++) acc[i][j] = 0.f;

    for (int t0 = 0; t0 < S; t0 += 64) {
        __syncthreads();
        #pragma unroll
        for (int it = 0; it < 4; it++) {
            int r = lr + it * 16;
            float4 a = *(const float4*)(Ab + (size_t)(s0 + r) * S + t0 + lc4);
            ast[lc4 + 0][r] = a.x; ast[lc4 + 1][r] = a.y;
            ast[lc4 + 2][r] = a.z; ast[lc4 + 3][r] = a.w;
            float4 vv = *(const float4*)(Vb + (size_t)(t0 + r) * D + lc4);
            *(float4*)&vs[r][lc4] = vv;
        }
        __syncthreads();
        #pragma unroll 8
        for (int t = 0; t < 64; t++) {
            float a[4], w[4];
            #pragma unroll
            for (int i = 0; i < 4; i++) a[i] = ast[t][ty * 4 + i];
            #pragma unroll
            for (int j = 0; j < 4; j++) w[j] = vs[t][tx * 4 + j];
            #pragma unroll
            for (int i = 0; i < 4; i++)
                #pragma unroll
                for (int j = 0; j < 4; j++)
                    acc[i][j] = fmaf(a[i], w[j], acc[i][j]);
        }
    }

    #pragma unroll
    for (int i = 0; i < 4; i++) {
        #pragma unroll
        for (int j = 0; j < 4; j++) {
            float v = acc[i][j];
            if (EPI == 1) {
                float sv = sqrtf(v + EPSV) + EPSV;  // y_scale + eps
                v = sv * sv;                         // (merge(y_scale)+eps)^2
            }
            Yb[(size_t)(s0 + ty * 4 + i) * D + tx * 4 + j] = v;
        }
    }
}

// ---------------------------------------------------------------------------
extern "C" void kernel_launch(void* const* d_in, const int* in_sizes, int n_in,
                              void* d_out, int out_size)
{
    const float* q_loc   = (const float*)d_in[0];
    // q_scale (d_in[1]) unused: score variance is a constant in the reference
    const float* k_loc   = (const float*)d_in[2];
    // k_scale (d_in[3]) unused
    const float* v_loc   = (const float*)d_in[4];
    const float* v_scale = (const float*)d_in[5];
    const float* Wq = (const float*)d_in[6];
    const float* bq = (const float*)d_in[7];
    const float* Wk = (const float*)d_in[8];
    const float* bk = (const float*)d_in[9];
    const float* Wv = (const float*)d_in[10];
    const float* bv = (const float*)d_in[11];
    const float* Wo = (const float*)d_in[12];
    const float* bo = (const float*)d_in[13];
    const float* tau = (const float*)d_in[14];

    float* out_loc   = (float*)d_out;
    float* out_scale = (float*)d_out + PROJ_ELEMS;

    float *qm, *km, *vm, *vvar, *ym, *pp, *lg, *amu, *avar;
    cudaGetSymbolAddress((void**)&qm,   g_qm);
    cudaGetSymbolAddress((void**)&km,   g_km);
    cudaGetSymbolAddress((void**)&vm,   g_vm);
    cudaGetSymbolAddress((void**)&vvar, g_vvar);
    cudaGetSymbolAddress((void**)&ym,   g_ym);
    cudaGetSymbolAddress((void**)&pp,   g_p);
    cudaGetSymbolAddress((void**)&lg,   g_logits);
    cudaGetSymbolAddress((void**)&amu,  g_amu);
    cudaGetSymbolAddress((void**)&avar, g_avar);

    const dim3 gthr(256);
    const dim3 ggrid(D / 128, BS / 128);   // (8, 16)

    // Projections (mean paths + V variance path). q/k scale projections are dead code.
    gemm_nt<false, false, 0><<<ggrid, gthr>>>(qm, q_loc, Wq, bq, BS, D, D);
    gemm_nt<false, false, 0><<<ggrid, gthr>>>(km, k_loc, Wk, bk, BS, D, D);
    gemm_nt<false, false, 0><<<ggrid, gthr>>>(vm, v_loc, Wv, bv, BS, D, D);
    gemm_nt<true,  true,  1><<<ggrid, gthr>>>(vvar, v_scale, Wv, nullptr, BS, D, D);

    // Attention logits, dual softmax, AV (mean + variance)
    qk_kernel<<<dim3(S / 64, S / 64, B * H), gthr>>>(lg, qm, km, tau);
    softmax_kernel<<<B * H * S, gthr>>>(amu, avar, lg, tau);
    av_kernel<0><<<dim3(S / 64, B * H), gthr>>>(ym, amu, vm);
    av_kernel<1><<<dim3(S / 64, B * H), gthr>>>(pp, avar, vvar);

    // Output projections: mean (+bias) and scale (sqrt of p @ Wo^2^T)
    gemm_nt<false, false, 0><<<ggrid, gthr>>>(out_loc,   ym, Wo, bo,      BS, D, D);
    gemm_nt<false, true,  2><<<ggrid, gthr>>>(out_scale, pp, Wo, nullptr, BS, D, D);
}

// round 4
// speedup vs baseline: 1.7506x; 1.7506x over previous
#include <cuda_runtime.h>
#include <cuda_bf16.h>
#include <math.h>
#include <stdint.h>

#define EPSV 1e-6f
using bf16 = __nv_bfloat16;

constexpr int B = 2, S = 1024, D = 1024, H = 16, HD = 64;
constexpr int BS = B * S;                         // 2048
constexpr size_t PROJ = (size_t)BS * D;           // 2M
constexpr size_t ATTN = (size_t)B * H * S * S;    // 32M
constexpr size_t WSZ  = (size_t)D * D;            // 1M

// ---------------- scratch (device globals; no dynamic allocation) ----------
__device__ float g_qm[PROJ], g_km[PROJ], g_vm[PROJ], g_vvar[PROJ];
__device__ float g_logits[ATTN], g_amu[ATTN], g_avar[ATTN];
// bf16 hi/lo split activations
__device__ bf16 g_qh[PROJ], g_ql[PROJ], g_kh[PROJ], g_kl[PROJ];
__device__ bf16 g_vh[PROJ], g_vl[PROJ], g_vsh[PROJ], g_vsl[PROJ];
__device__ bf16 g_ymh[PROJ], g_yml[PROJ], g_pph[PROJ], g_ppl[PROJ];
// bf16 hi/lo split weights
__device__ bf16 g_wqh[WSZ], g_wql[WSZ], g_wkh[WSZ], g_wkl[WSZ];
__device__ bf16 g_wvh[WSZ], g_wvl[WSZ], g_wvsh[WSZ], g_wvsl[WSZ];
__device__ bf16 g_woh[WSZ], g_wol[WSZ], g_wosh[WSZ], g_wosl[WSZ];

// ---------------- helpers --------------------------------------------------
__device__ __forceinline__ uint32_t smem_u32(const void* p) {
    uint32_t a;
    asm("{ .reg .u64 t; cvta.to.shared.u64 t, %1; cvt.u32.u64 %0, t; }" : "=r"(a) : "l"(p));
    return a;
}
#define SWZ(o) ((o) ^ (((o) >> 3) & 0x70))

__device__ __forceinline__ void cp16(uint32_t dst, const void* src) {
    asm volatile("cp.async.cg.shared.global [%0], [%1], 16;" :: "r"(dst), "l"(src));
}
__device__ __forceinline__ void cp_commit() {
    asm volatile("cp.async.commit_group;" ::: "memory");
}
template<int N>
__device__ __forceinline__ void cp_wait() {
    asm volatile("cp.async.wait_group %0;" :: "n"(N) : "memory");
}
__device__ __forceinline__ void ldsm4(uint32_t& r0, uint32_t& r1, uint32_t& r2, uint32_t& r3,
                                      uint32_t addr) {
    asm volatile("ldmatrix.sync.aligned.m8n8.x4.shared.b16 {%0,%1,%2,%3}, [%4];"
                 : "=r"(r0), "=r"(r1), "=r"(r2), "=r"(r3) : "r"(addr));
}
__device__ __forceinline__ void mma16816(float* d, const uint32_t* a, const uint32_t* b) {
    asm volatile(
        "mma.sync.aligned.m16n8k16.row.col.f32.bf16.bf16.f32 "
        "{%0,%1,%2,%3}, {%4,%5,%6,%7}, {%8,%9}, {%0,%1,%2,%3};"
        : "+f"(d[0]), "+f"(d[1]), "+f"(d[2]), "+f"(d[3])
        : "r"(a[0]), "r"(a[1]), "r"(a[2]), "r"(a[3]), "r"(b[0]), "r"(b[1]));
}
__device__ __forceinline__ void split2(float v, bf16& h, bf16& l) {
    h = __float2bfloat16(v);
    l = __float2bfloat16(v - __bfloat162float(h));
}

// ---------------------------------------------------------------------------
// convert_all: fp32 -> (bf16 hi, bf16 lo), optional square, 10 regions
// ---------------------------------------------------------------------------
struct CvtParams {
    const float* src[10];
    bf16* hi[10];
    bf16* lo[10];
    int n[10];
    int sq[10];
};

__global__ void __launch_bounds__(256) convert_all(CvtParams P) {
    const int r = blockIdx.y;
    const int i4 = (blockIdx.x * 256 + threadIdx.x) * 4;
    if (i4 >= P.n[r]) return;
    float4 v = *(const float4*)(P.src[r] + i4);
    if (P.sq[r]) { v.x *= v.x; v.y *= v.y; v.z *= v.z; v.w *= v.w; }
    bf16 h0, h1, h2, h3, l0, l1, l2, l3;
    split2(v.x, h0, l0); split2(v.y, h1, l1); split2(v.z, h2, l2); split2(v.w, h3, l3);
    __nv_bfloat162 a, b;
    a.x = h0; a.y = h1; b.x = h2; b.y = h3;
    *(__nv_bfloat162*)(P.hi[r] + i4) = a;
    *(__nv_bfloat162*)(P.hi[r] + i4 + 2) = b;
    a.x = l0; a.y = l1; b.x = l2; b.y = l3;
    *(__nv_bfloat162*)(P.lo[r] + i4) = a;
    *(__nv_bfloat162*)(P.lo[r] + i4 + 2) = b;
}

// ---------------------------------------------------------------------------
// gemm_mma: C[2048,1024] = (Ah+Al)[M,K=1024] * (Bh+Bl)[N,K]^T  (bf16x3, HMMA)
// 128x128 CTA tile, BK=64 chunks, cp.async double buffer, SW128-swizzled smem.
// 8 warps as 4(M) x 2(N): each warp 32x64 = 2x8 m16n8k16 tiles, 3 passes.
// EPI: 0 = +bias[n];  1 = (sqrt(acc)+eps)^2;  2 = sqrt(acc)
// ---------------------------------------------------------------------------
constexpr int GK = 1024;
constexpr int GN = 1024;
constexpr uint32_t TILE_B  = 16384;                 // one 128x64 bf16 tile
constexpr uint32_t STAGE_B = 4 * TILE_B;            // Ah, Al, Bh, Bl
constexpr uint32_t GSMEM   = 2 * STAGE_B + 1024;    // + alignment slack

template<int EPI>
__global__ void __launch_bounds__(256, 1) gemm_mma(
    float* __restrict__ C,
    const bf16* __restrict__ Ah, const bf16* __restrict__ Al,
    const bf16* __restrict__ Bh, const bf16* __restrict__ Bl,
    const float* __restrict__ bias)
{
    extern __shared__ char dsraw[];
    char* dsm = (char*)(((uintptr_t)dsraw + 1023) & ~(uintptr_t)1023);
    const uint32_t base = smem_u32(dsm);

    const int tid  = threadIdx.x;
    const int wid  = tid >> 5;
    const int lane = tid & 31;
    const int wm = wid & 3;           // 0..3  -> rows wm*32
    const int wn = wid >> 2;          // 0..1  -> cols wn*64
    const int row0 = blockIdx.y * 128;
    const int col0 = blockIdx.x * 128;

    // loader mapping: 2 threads per row, 4 x 16B segments each
    const int lr = tid >> 1;                  // 0..127
    const int ls0 = (tid & 1) * 4;            // 0 or 4
    const size_t aoff = (size_t)(row0 + lr) * GK;
    const size_t boff = (size_t)(col0 + lr) * GK;

    auto load_chunk = [&](int c, int st) {
        const uint32_t sb = base + st * STAGE_B;
        const int k0 = c * 64;
        #pragma unroll
        for (int i = 0; i < 4; i++) {
            const int sg = ls0 + i;           // 0..7
            const uint32_t so = SWZ((uint32_t)(lr * 128 + sg * 16));
            const size_t ga = aoff + k0 + sg * 8;
            const size_t gb = boff + k0 + sg * 8;
            cp16(sb + so,              Ah + ga);
            cp16(sb + TILE_B + so,     Al + ga);
            cp16(sb + 2 * TILE_B + so, Bh + gb);
            cp16(sb + 3 * TILE_B + so, Bl + gb);
        }
    };

    float acc[2][8][4];
    #pragma unroll
    for (int mi = 0; mi < 2; mi++)
        #pragma unroll
        for (int ni = 0; ni < 8; ni++)
            #pragma unroll
            for (int q = 0; q < 4; q++) acc[mi][ni][q] = 0.f;

    // ldmatrix address components (within a stage)
    // A: row = wm*32 + mi*16 + (lane&15), kcol = k0 + (lane>>4)*8
    const int a_r = wm * 32 + (lane & 15);
    const int a_kseg = (lane >> 4);           // 0/1 -> +8 cols
    // B x4 over an n-tile pair p: row = wn*64 + p*16 + ((lane>>4)&1)*8 + (lane&7)
    //                             kcol = k0 + ((lane>>3)&1)*8
    const int b_r = wn * 64 + ((lane >> 4) & 1) * 8 + (lane & 7);
    const int b_kseg = (lane >> 3) & 1;

    load_chunk(0, 0);
    cp_commit();

    for (int c = 0; c < 16; c++) {
        const int st = c & 1;
        if (c + 1 < 16) { load_chunk(c + 1, st ^ 1); cp_commit(); cp_wait<1>(); }
        else            { cp_wait<0>(); }
        __syncthreads();

        const uint32_t sA = base + st * STAGE_B;
        const uint32_t sB = sA + 2 * TILE_B;

        #pragma unroll
        for (int ks = 0; ks < 4; ks++) {
            const int k0 = ks * 16;
            // B fragments: 8 n-tiles (4 ldmatrix.x4 per precision)
            uint32_t bh[16], bl[16];
            #pragma unroll
            for (int p = 0; p < 4; p++) {
                const uint32_t bo = SWZ((uint32_t)((b_r + p * 16) * 128 +
                                                   (k0 + b_kseg * 8) * 2));
                ldsm4(bh[4 * p], bh[4 * p + 1], bh[4 * p + 2], bh[4 * p + 3], sB + bo);
                ldsm4(bl[4 * p], bl[4 * p + 1], bl[4 * p + 2], bl[4 * p + 3],
                      sB + TILE_B + bo);
            }
            #pragma unroll
            for (int mi = 0; mi < 2; mi++) {
                const uint32_t ao = SWZ((uint32_t)((a_r + mi * 16) * 128 +
                                                   (k0 + a_kseg * 8) * 2));
                uint32_t ah[4], al[4];
                ldsm4(ah[0], ah[1], ah[2], ah[3], sA + ao);
                ldsm4(al[0], al[1], al[2], al[3], sA + TILE_B + ao);
                #pragma unroll
                for (int ni = 0; ni < 8; ni++) {
                    mma16816(acc[mi][ni], ah, &bh[ni * 2]);
                    mma16816(acc[mi][ni], ah, &bl[ni * 2]);
                    mma16816(acc[mi][ni], al, &bh[ni * 2]);
                }
            }
        }
        __syncthreads();
    }

    // epilogue: direct global stores (float2 per thread per half-tile)
    const int er = lane >> 2;            // 0..7
    const int ec = (lane & 3) * 2;       // 0,2,4,6
    #pragma unroll
    for (int mi = 0; mi < 2; mi++) {
        #pragma unroll
        for (int ni = 0; ni < 8; ni++) {
            const int gr = row0 + wm * 32 + mi * 16 + er;
            const int gc = col0 + wn * 64 + ni * 8 + ec;
            float v0 = acc[mi][ni][0], v1 = acc[mi][ni][1];
            float v2 = acc[mi][ni][2], v3 = acc[mi][ni][3];
            if (EPI == 0) {
                v0 += bias[gc]; v1 += bias[gc + 1];
                v2 += bias[gc]; v3 += bias[gc + 1];
            } else if (EPI == 1) {
                float s;
                s = sqrtf(v0) + EPSV; v0 = s * s;
                s = sqrtf(v1) + EPSV; v1 = s * s;
                s = sqrtf(v2) + EPSV; v2 = s * s;
                s = sqrtf(v3) + EPSV; v3 = s * s;
            } else {
                v0 = sqrtf(v0); v1 = sqrtf(v1); v2 = sqrtf(v2); v3 = sqrtf(v3);
            }
            float2 w0 = {v0, v1}, w1 = {v2, v3};
            *(float2*)(C + (size_t)gr * GN + gc)       = w0;
            *(float2*)(C + (size_t)(gr + 8) * GN + gc) = w1;
        }
    }
}

// ---------------------------------------------------------------------------
// qk_batched: logits[bh, s, t] = (qm_head[s,:] . km_head[t,:]) / (8*tau)
// 128x128 tile, 8x8 microtile, K=64. grid (8, 8, 32).
// ---------------------------------------------------------------------------
__global__ void __launch_bounds__(256) qk_batched(
    float* __restrict__ logits, const float* __restrict__ qm,
    const float* __restrict__ km, const float* __restrict__ tau)
{
    __shared__ float as[8][132];
    __shared__ float bs[8][132];

    const int tid = threadIdx.x;
    const int bh = blockIdx.z;
    const int b = bh >> 4, h = bh & 15;
    const float* A  = qm + (size_t)b * S * D + h * HD;
    const float* Bm = km + (size_t)b * S * D + h * HD;

    const int s0 = blockIdx.y * 128, t0 = blockIdx.x * 128;
    const int arow = tid >> 1;
    const int ac4  = (tid & 1) * 4;
    const float* Ap = A  + (size_t)(s0 + arow) * D + ac4;
    const float* Bp = Bm + (size_t)(t0 + arow) * D + ac4;

    const int ty = tid >> 4, tx = tid & 15;

    float acc[8][8];
    #pragma unroll
    for (int i = 0; i < 8; i++)
        #pragma unroll
        for (int j = 0; j < 8; j++) acc[i][j] = 0.f;

    for (int k0 = 0; k0 < HD; k0 += 8) {
        float4 av = *(const float4*)(Ap + k0);
        float4 bv = *(const float4*)(Bp + k0);
        __syncthreads();
        as[ac4 + 0][arow] = av.x; as[ac4 + 1][arow] = av.y;
        as[ac4 + 2][arow] = av.z; as[ac4 + 3][arow] = av.w;
        bs[ac4 + 0][arow] = bv.x; bs[ac4 + 1][arow] = bv.y;
        bs[ac4 + 2][arow] = bv.z; bs[ac4 + 3][arow] = bv.w;
        __syncthreads();
        #pragma unroll
        for (int kk = 0; kk < 8; kk++) {
            float a[8], w[8];
            #pragma unroll
            for (int i = 0; i < 8; i++) a[i] = as[kk][ty * 8 + i];
            #pragma unroll
            for (int j = 0; j < 8; j++) w[j] = bs[kk][tx * 8 + j];
            #pragma unroll
            for (int i = 0; i < 8; i++)
                #pragma unroll
                for (int j = 0; j < 8; j++)
                    acc[i][j] = fmaf(a[i], w[j], acc[i][j]);
        }
    }

    const float scale = 1.f / (8.f * tau[0]);
    float* Lb = logits + (size_t)bh * S * S;
    #pragma unroll
    for (int i = 0; i < 8; i++)
        #pragma unroll
        for (int j = 0; j < 8; j++)
            Lb[(size_t)(s0 + ty * 8 + i) * S + t0 + tx * 8 + j] = acc[i][j] * scale;
}

// ---------------------------------------------------------------------------
// softmax (dual temperature)
// ---------------------------------------------------------------------------
__global__ void __launch_bounds__(256) softmax_kernel(
    float* __restrict__ amu, float* __restrict__ avar,
    const float* __restrict__ logits, const float* __restrict__ tau)
{
    __shared__ float shm[8], sh1[8], sh2[8];
    const int tid = threadIdx.x;
    const size_t row = blockIdx.x;
    const float4 v = ((const float4*)(logits + row * (size_t)S))[tid];

    float m = fmaxf(fmaxf(v.x, v.y), fmaxf(v.z, v.w));
    #pragma unroll
    for (int o = 16; o; o >>= 1) m = fmaxf(m, __shfl_xor_sync(0xffffffffu, m, o));
    if ((tid & 31) == 0) shm[tid >> 5] = m;
    __syncthreads();
    m = shm[tid & 7];
    #pragma unroll
    for (int o = 4; o; o >>= 1) m = fmaxf(m, __shfl_xor_sync(0xffffffffu, m, o));

    const float tv = tau[0];
    const float l_var = ((0.1f + EPSV) / 64.f + EPSV) / (tv * tv) + EPSV;
    const float invc = rsqrtf(1.f + 0.39269908169872414f * l_var);

    float4 e1, e2;
    e1.x = expf(v.x - m); e1.y = expf(v.y - m); e1.z = expf(v.z - m); e1.w = expf(v.w - m);
    e2.x = expf((v.x - m) * invc); e2.y = expf((v.y - m) * invc);
    e2.z = expf((v.z - m) * invc); e2.w = expf((v.w - m) * invc);

    float s1 = e1.x + e1.y + e1.z + e1.w;
    float s2 = e2.x + e2.y + e2.z + e2.w;
    #pragma unroll
    for (int o = 16; o; o >>= 1) {
        s1 += __shfl_xor_sync(0xffffffffu, s1, o);
        s2 += __shfl_xor_sync(0xffffffffu, s2, o);
    }
    if ((tid & 31) == 0) { sh1[tid >> 5] = s1; sh2[tid >> 5] = s2; }
    __syncthreads();
    s1 = sh1[tid & 7]; s2 = sh2[tid & 7];
    #pragma unroll
    for (int o = 4; o; o >>= 1) {
        s1 += __shfl_xor_sync(0xffffffffu, s1, o);
        s2 += __shfl_xor_sync(0xffffffffu, s2, o);
    }

    const float r1 = 1.f / s1, r2 = 1.f / s2;
    float4 mu4, var4;
    float t, r;
    t = e1.x * r1; r = e2.x * r2; mu4.x = t + r; var4.x = 1e-4f + r * (1.f - r) * l_var + EPSV;
    t = e1.y * r1; r = e2.y * r2; mu4.y = t + r; var4.y = 1e-4f + r * (1.f - r) * l_var + EPSV;
    t = e1.z * r1; r = e2.z * r2; mu4.z = t + r; var4.z = 1e-4f + r * (1.f - r) * l_var + EPSV;
    t = e1.w * r1; r = e2.w * r2; mu4.w = t + r; var4.w = 1e-4f + r * (1.f - r) * l_var + EPSV;

    ((float4*)(amu  + row * (size_t)S))[tid] = mu4;
    ((float4*)(avar + row * (size_t)S))[tid] = var4;
}

// ---------------------------------------------------------------------------
// av: Y[b, s, h*64+n] = sum_t Attn[bh,s,t] * V[b,t,h*64+n]
// 128(s) x 64(n) tile, K-chunks of 32, 8x4 microtile. Writes bf16 hi/lo.
// EPI: 0 = raw; 1 = (sqrt(acc+eps)+eps)^2
// ---------------------------------------------------------------------------
template<int EPI>
__global__ void __launch_bounds__(256) av_kernel(
    bf16* __restrict__ Yh, bf16* __restrict__ Yl,
    const float* __restrict__ Attn, const float* __restrict__ V)
{
    __shared__ float ast[32][136];   // [t][s]
    __shared__ float vs[32][68];     // [t][n]

    const int tid = threadIdx.x;
    const int bh = blockIdx.y;
    const int b = bh >> 4, h = bh & 15;
    const int s0 = blockIdx.x * 128;

    const float* Ab = Attn + (size_t)bh * S * S;
    const float* Vb = V + (size_t)b * S * D + h * HD;
    const size_t ybase = (size_t)b * S * D + h * HD;

    const int ty = tid >> 4;
    const int tx = tid & 15;
    const int fr = tid >> 1;
    const int fsegb = (tid & 1) * 4;

    float acc[8][4];
    #pragma unroll
    for (int i = 0; i < 8; i++)
        #pragma unroll
        for (int j = 0; j < 4; j++) acc[i][j] = 0.f;

    for (int t0 = 0; t0 < S; t0 += 32) {
        __syncthreads();
        #pragma unroll
        for (int i = 0; i < 4; i++) {
            const int seg = fsegb + i;
            float4 f = *(const float4*)(Ab + (size_t)(s0 + fr) * S + t0 + seg * 4);
            ast[seg * 4 + 0][fr] = f.x;
            ast[seg * 4 + 1][fr] = f.y;
            ast[seg * 4 + 2][fr] = f.z;
            ast[seg * 4 + 3][fr] = f.w;
        }
        #pragma unroll
        for (int i = 0; i < 2; i++) {
            const int vi = i * 256 + tid;
            const int vr = vi >> 4;
            const int vc = (vi & 15) * 4;
            float4 f = *(const float4*)(Vb + (size_t)(t0 + vr) * D + vc);
            *(float4*)&vs[vr][vc] = f;
        }
        __syncthreads();
        #pragma unroll 4
        for (int k = 0; k < 32; k++) {
            float a[8], w[4];
            *(float4*)&a[0] = *(const float4*)&ast[k][ty * 8];
            *(float4*)&a[4] = *(const float4*)&ast[k][ty * 8 + 4];
            *(float4*)&w[0] = *(const float4*)&vs[k][tx * 4];
            #pragma unroll
            for (int i = 0; i < 8; i++)
                #pragma unroll
                for (int j = 0; j < 4; j++)
                    acc[i][j] = fmaf(a[i], w[j], acc[i][j]);
        }
    }

    #pragma unroll
    for (int i = 0; i < 8; i++) {
        #pragma unroll
        for (int j = 0; j < 4; j++) {
            float v = acc[i][j];
            if (EPI == 1) {
                float sv = sqrtf(v + EPSV) + EPSV;
                v = sv * sv;
            }
            bf16 hh, ll;
            split2(v, hh, ll);
            const size_t idx = ybase + (size_t)(s0 + ty * 8 + i) * D + tx * 4 + j;
            Yh[idx] = hh;
            Yl[idx] = ll;
        }
    }
}

// ---------------------------------------------------------------------------
extern "C" void kernel_launch(void* const* d_in, const int* in_sizes, int n_in,
                              void* d_out, int out_size)
{
    const float* q_loc   = (const float*)d_in[0];
    const float* k_loc   = (const float*)d_in[2];
    const float* v_loc   = (const float*)d_in[4];
    const float* v_scale = (const float*)d_in[5];
    const float* Wq = (const float*)d_in[6];
    const float* bq = (const float*)d_in[7];
    const float* Wk = (const float*)d_in[8];
    const float* bk = (const float*)d_in[9];
    const float* Wv = (const float*)d_in[10];
    const float* bv = (const float*)d_in[11];
    const float* Wo = (const float*)d_in[12];
    const float* bo = (const float*)d_in[13];
    const float* tau = (const float*)d_in[14];

    float* out_loc   = (float*)d_out;
    float* out_scale = (float*)d_out + PROJ;

    float *qm, *km, *vm, *vvar, *lg, *amu, *avar;
    cudaGetSymbolAddress((void**)&qm, g_qm);     cudaGetSymbolAddress((void**)&km, g_km);
    cudaGetSymbolAddress((void**)&vm, g_vm);     cudaGetSymbolAddress((void**)&vvar, g_vvar);
    cudaGetSymbolAddress((void**)&lg, g_logits); cudaGetSymbolAddress((void**)&amu, g_amu);
    cudaGetSymbolAddress((void**)&avar, g_avar);
    bf16 *qh,*ql,*kh,*kl,*vh,*vl,*vsh,*vsl,*ymh,*yml,*pph,*ppl;
    cudaGetSymbolAddress((void**)&qh, g_qh);   cudaGetSymbolAddress((void**)&ql, g_ql);
    cudaGetSymbolAddress((void**)&kh, g_kh);   cudaGetSymbolAddress((void**)&kl, g_kl);
    cudaGetSymbolAddress((void**)&vh, g_vh);   cudaGetSymbolAddress((void**)&vl, g_vl);
    cudaGetSymbolAddress((void**)&vsh, g_vsh); cudaGetSymbolAddress((void**)&vsl, g_vsl);
    cudaGetSymbolAddress((void**)&ymh, g_ymh); cudaGetSymbolAddress((void**)&yml, g_yml);
    cudaGetSymbolAddress((void**)&pph, g_pph); cudaGetSymbolAddress((void**)&ppl, g_ppl);
    bf16 *wqh,*wql,*wkh,*wkl,*wvh,*wvl,*wvsh,*wvsl,*woh,*wol,*wosh,*wosl;
    cudaGetSymbolAddress((void**)&wqh, g_wqh);   cudaGetSymbolAddress((void**)&wql, g_wql);
    cudaGetSymbolAddress((void**)&wkh, g_wkh);   cudaGetSymbolAddress((void**)&wkl, g_wkl);
    cudaGetSymbolAddress((void**)&wvh, g_wvh);   cudaGetSymbolAddress((void**)&wvl, g_wvl);
    cudaGetSymbolAddress((void**)&wvsh, g_wvsh); cudaGetSymbolAddress((void**)&wvsl, g_wvsl);
    cudaGetSymbolAddress((void**)&woh, g_woh);   cudaGetSymbolAddress((void**)&wol, g_wol);
    cudaGetSymbolAddress((void**)&wosh, g_wosh); cudaGetSymbolAddress((void**)&wosl, g_wosl);

    cudaFuncSetAttribute(gemm_mma<0>, cudaFuncAttributeMaxDynamicSharedMemorySize, GSMEM);
    cudaFuncSetAttribute(gemm_mma<1>, cudaFuncAttributeMaxDynamicSharedMemorySize, GSMEM);
    cudaFuncSetAttribute(gemm_mma<2>, cudaFuncAttributeMaxDynamicSharedMemorySize, GSMEM);

    // hi/lo conversion of all inputs (one launch)
    CvtParams P;
    const int PN = (int)PROJ, WN = (int)WSZ;
    P.src[0] = q_loc;   P.hi[0] = qh;   P.lo[0] = ql;   P.n[0] = PN; P.sq[0] = 0;
    P.src[1] = k_loc;   P.hi[1] = kh;   P.lo[1] = kl;   P.n[1] = PN; P.sq[1] = 0;
    P.src[2] = v_loc;   P.hi[2] = vh;   P.lo[2] = vl;   P.n[2] = PN; P.sq[2] = 0;
    P.src[3] = v_scale; P.hi[3] = vsh;  P.lo[3] = vsl;  P.n[3] = PN; P.sq[3] = 1;
    P.src[4] = Wq;      P.hi[4] = wqh;  P.lo[4] = wql;  P.n[4] = WN; P.sq[4] = 0;
    P.src[5] = Wk;      P.hi[5] = wkh;  P.lo[5] = wkl;  P.n[5] = WN; P.sq[5] = 0;
    P.src[6] = Wv;      P.hi[6] = wvh;  P.lo[6] = wvl;  P.n[6] = WN; P.sq[6] = 0;
    P.src[7] = Wv;      P.hi[7] = wvsh; P.lo[7] = wvsl; P.n[7] = WN; P.sq[7] = 1;
    P.src[8] = Wo;      P.hi[8] = woh;  P.lo[8] = wol;  P.n[8] = WN; P.sq[8] = 0;
    P.src[9] = Wo;      P.hi[9] = wosh; P.lo[9] = wosl; P.n[9] = WN; P.sq[9] = 1;
    convert_all<<<dim3(PN / 1024, 10), 256>>>(P);

    const dim3 gg(GN / 128, BS / 128);   // (8, 16)

    // HMMA projections
    gemm_mma<0><<<gg, 256, GSMEM>>>(qm,   qh,  ql,  wqh,  wql,  bq);
    gemm_mma<0><<<gg, 256, GSMEM>>>(km,   kh,  kl,  wkh,  wkl,  bk);
    gemm_mma<0><<<gg, 256, GSMEM>>>(vm,   vh,  vl,  wvh,  wvl,  bv);
    gemm_mma<1><<<gg, 256, GSMEM>>>(vvar, vsh, vsl, wvsh, wvsl, nullptr);

    // attention (SIMT fp32)
    qk_batched<<<dim3(S / 128, S / 128, B * H), 256>>>(lg, qm, km, tau);
    softmax_kernel<<<B * H * S, 256>>>(amu, avar, lg, tau);
    av_kernel<0><<<dim3(S / 128, B * H), 256>>>(ymh, yml, amu, vm);
    av_kernel<1><<<dim3(S / 128, B * H), 256>>>(pph, ppl, avar, vvar);

    // HMMA output projections
    gemm_mma<0><<<gg, 256, GSMEM>>>(out_loc,   ymh, yml, woh,  wol,  bo);
    gemm_mma<2><<<gg, 256, GSMEM>>>(out_scale, pph, ppl, wosh, wosl, nullptr);
}